// round 3
// baseline (speedup 1.0000x reference)
#include <cuda_runtime.h>

// LIF neuron scan: T=8, leaky integrate + threshold + reset-by-subtraction.
// x: [T, N] fp32, N = 32*128*32*32 = 4,194,304 (N4 = 1,048,576 float4s).
// Pure streaming, HBM-bound (268 MB irreducible traffic).
//
// R3: persistent grid-stride. 1024 blocks x 256 threads x 4 iterations covers
// N4 exactly -> single wave (no wave-transition overhead, no per-wave
// cross-CTA L1tex-queue spread compounding, no partial-wave tail).
// Interleaved per-timestep body keeps regs ~32 (high occupancy) and moderate
// MLP_p1 (low spread per the B300 spr_max model).

#define T_STEPS 8
#define N_ELEM  (32 * 128 * 32 * 32)
#define N4      (N_ELEM / 4)
#define BLOCKS  1024
#define THREADS 256
#define ITERS   (N4 / (BLOCKS * THREADS))   // exactly 4

__global__ __launch_bounds__(THREADS) void lif_kernel(
    const float4* __restrict__ x,
    const float*  __restrict__ vth_ptr,
    float4*       __restrict__ out)
{
    // no-grad clamp: relu(Vth - bound) + bound
    float Vth = vth_ptr[0];
    Vth = fmaxf(Vth - 0.0005f, 0.0f) + 0.0005f;

    const float beta = 0.9512294531f;   // fp32 nearest to exp(-0.05)
    const float omb  = 1.0f - beta;
    const float thr  = 0.3f * Vth;
    const float sval = Vth * 20.0f;     // Vth / DELTA_T

    const int stride = BLOCKS * THREADS;
    int idx = blockIdx.x * THREADS + threadIdx.x;

#pragma unroll 1
    for (int it = 0; it < ITERS; it++, idx += stride) {
        float mx = 0.f, my = 0.f, mz = 0.f, mw = 0.f;

#pragma unroll
        for (int t = 0; t < T_STEPS; t++) {
            float4 xt = __ldcs(&x[(size_t)t * N4 + idx]);

            mx = beta * mx + omb * xt.x;
            my = beta * my + omb * xt.y;
            mz = beta * mz + omb * xt.z;
            mw = beta * mw + omb * xt.w;

            float4 o;
            if (mx >= thr) { o.x = sval; mx -= Vth; } else { o.x = 0.f; }
            if (my >= thr) { o.y = sval; my -= Vth; } else { o.y = 0.f; }
            if (mz >= thr) { o.z = sval; mz -= Vth; } else { o.z = 0.f; }
            if (mw >= thr) { o.w = sval; mw -= Vth; } else { o.w = 0.f; }

            __stcs(&out[(size_t)t * N4 + idx], o);
        }
    }
}

extern "C" void kernel_launch(void* const* d_in, const int* in_sizes, int n_in,
                              void* d_out, int out_size) {
    const float4* x   = (const float4*)d_in[0];
    const float*  vth = (const float*)d_in[1];
    float4*       out = (float4*)d_out;

    lif_kernel<<<BLOCKS, THREADS>>>(x, vth, out);
}

// round 5
// speedup vs baseline: 1.0558x; 1.0558x over previous
#include <cuda_runtime.h>

// LIF neuron scan: T=8, leaky integrate + threshold + reset-by-subtraction.
// x: [T, N] fp32, N = 32*128*32*32 = 4,194,304 (N4 = 1,048,576 float4s).
// HBM-bound streaming kernel.
//
// R4: R1 structure (best measured: 4096 one-shot CTAs, interleaved
// load->scan->store) + asymmetric cache policy:
//   - reads  __ldcs (evict-first: zero reuse, don't pollute L2)
//   - writes default write-back (NOT __stcs): dirty output lines that stay
//     resident in the 126MB L2 across graph replays are overwritten before
//     eviction and never cost DRAM write bandwidth (R1 ncu already showed
//     ~54MB of the 268MB absorbed by L2; this maximizes that effect).

#define T_STEPS 8
#define N_ELEM  (32 * 128 * 32 * 32)
#define N4      (N_ELEM / 4)

__global__ __launch_bounds__(256) void lif_kernel(
    const float4* __restrict__ x,
    const float*  __restrict__ vth_ptr,
    float4*       __restrict__ out)
{
    int idx = blockIdx.x * blockDim.x + threadIdx.x;

    // no-grad clamp: relu(Vth - bound) + bound
    float Vth = vth_ptr[0];
    Vth = fmaxf(Vth - 0.0005f, 0.0f) + 0.0005f;

    const float beta = 0.9512294531f;   // fp32 nearest to exp(-0.05)
    const float omb  = 1.0f - beta;
    const float thr  = 0.3f * Vth;
    const float sval = Vth * 20.0f;     // Vth / DELTA_T

    float mx = 0.f, my = 0.f, mz = 0.f, mw = 0.f;

#pragma unroll
    for (int t = 0; t < T_STEPS; t++) {
        float4 xt = __ldcs(&x[(size_t)t * N4 + idx]);

        mx = beta * mx + omb * xt.x;
        my = beta * my + omb * xt.y;
        mz = beta * mz + omb * xt.z;
        mw = beta * mw + omb * xt.w;

        float4 o;
        if (mx >= thr) { o.x = sval; mx -= Vth; } else { o.x = 0.f; }
        if (my >= thr) { o.y = sval; my -= Vth; } else { o.y = 0.f; }
        if (mz >= thr) { o.z = sval; mz -= Vth; } else { o.z = 0.f; }
        if (mw >= thr) { o.w = sval; mw -= Vth; } else { o.w = 0.f; }

        out[(size_t)t * N4 + idx] = o;   // default write-back: let L2 keep it
    }
}

extern "C" void kernel_launch(void* const* d_in, const int* in_sizes, int n_in,
                              void* d_out, int out_size) {
    const float4* x   = (const float4*)d_in[0];
    const float*  vth = (const float*)d_in[1];
    float4*       out = (float4*)d_out;

    lif_kernel<<<N4 / 256, 256>>>(x, vth, out);
}